// round 15
// baseline (speedup 1.0000x reference)
#include <cuda_runtime.h>
#include <math.h>

#define C_DIM 1280
#define HW    9216
#define WIMG  96
#define N_ID  16
#define D_IN  512
#define B_SZ  8
#define M_ROWS 128
#define KCHUNK 8

#define GCH 8                 // channels per cp.async group
#define NGRP (C_DIM / GCH)    // 160
#define RING_FLOATS (3 * GCH * 128 * 2)   // 3 stages * 8 ch * 128 thr * 2 px = 6144
#define SMEM_FLOATS (C_DIM * N_ID + RING_FLOATS)

// ---------------- scratch ----------------
__device__ float g_h[M_ROWS * C_DIM];
__device__ float g_part[KCHUNK * M_ROWS * C_DIM];
__device__ float g_pt[B_SZ * C_DIM * N_ID];    // projected [b][c][n]

// ---------------- f32x2 helpers ----------------
__device__ __forceinline__ unsigned long long fma2(unsigned long long a,
                                                   unsigned long long b,
                                                   unsigned long long c) {
    unsigned long long d;
    asm("fma.rn.f32x2 %0, %1, %2, %3;" : "=l"(d) : "l"(a), "l"(b), "l"(c));
    return d;
}
__device__ __forceinline__ unsigned long long packf2(float lo, float hi) {
    unsigned long long r;
    asm("mov.b64 %0, {%1, %2};" : "=l"(r) : "f"(lo), "f"(hi));
    return r;
}
__device__ __forceinline__ float2 unpackf2(unsigned long long v) {
    float2 r;
    asm("mov.b64 {%0, %1}, %2;" : "=f"(r.x), "=f"(r.y) : "l"(v));
    return r;
}

// ---------------- 32x64 tile GEMM core (unchanged from champion) ----------------
template <bool GELU>
__device__ __forceinline__ void gemm32x64(const float* __restrict__ A, int ldA,
                                          const float* __restrict__ Wm,
                                          const float* __restrict__ bias,
                                          float* __restrict__ Out,
                                          int kt0, int ktEnd) {
    __shared__ float sAt[32][34];
    __shared__ float sB[32][68];
    int t = threadIdx.x;
    int tj = t & 15;
    int tr = t >> 4;
    int rowBase = blockIdx.y * 32;
    int colBase = blockIdx.x * 64;

    unsigned long long acc[2][2];
    acc[0][0] = acc[0][1] = acc[1][0] = acc[1][1] = 0ull;

    for (int kt = kt0; kt < ktEnd; kt += 32) {
#pragma unroll
        for (int s = 0; s < 4; s++) {
            int idx = t + s * 256;
            int row = idx >> 5, kk = idx & 31;
            sAt[kk][row] = A[(size_t)(rowBase + row) * ldA + kt + kk];
        }
#pragma unroll
        for (int s = 0; s < 8; s++) {
            int idx = t + s * 256;
            int r = idx >> 6, c = idx & 63;
            sB[r][c] = Wm[(size_t)(kt + r) * C_DIM + colBase + c];
        }
        __syncthreads();
#pragma unroll
        for (int k = 0; k < 32; k++) {
            float2 av = *(const float2*)&sAt[k][tr * 2];
            ulonglong2 bv = *(const ulonglong2*)&sB[k][tj * 4];
            unsigned long long a0 = packf2(av.x, av.x);
            unsigned long long a1 = packf2(av.y, av.y);
            acc[0][0] = fma2(a0, bv.x, acc[0][0]);
            acc[0][1] = fma2(a0, bv.y, acc[0][1]);
            acc[1][0] = fma2(a1, bv.x, acc[1][0]);
            acc[1][1] = fma2(a1, bv.y, acc[1][1]);
        }
        __syncthreads();
    }
#pragma unroll
    for (int r = 0; r < 2; r++) {
        float2 v0 = unpackf2(acc[r][0]);
        float2 v1 = unpackf2(acc[r][1]);
        float vals[4] = {v0.x, v0.y, v1.x, v1.y};
        int row = rowBase + tr * 2 + r;
        int col = colBase + tj * 4;
        float4 o;
        float* ov = (float*)&o;
#pragma unroll
        for (int i = 0; i < 4; i++) {
            float v = vals[i] + (bias ? bias[col + i] : 0.f);
            if (GELU) v = 0.5f * v * (1.f + erff(v * 0.70710678f));
            ov[i] = v;
        }
        *(float4*)&Out[(size_t)row * C_DIM + col] = o;
    }
}

__global__ __launch_bounds__(256) void mlp1_kernel(const float* __restrict__ E,
                                                   const float* __restrict__ W1,
                                                   const float* __restrict__ b1) {
    gemm32x64<true>(E, D_IN, W1, b1, g_h, 0, D_IN);
}
__global__ __launch_bounds__(256) void mlp2_kernel(const float* __restrict__ W2) {
    int z = blockIdx.z;
    int kspan = C_DIM / KCHUNK;
    gemm32x64<false>(g_h, C_DIM, W2, nullptr,
                     g_part + (size_t)z * M_ROWS * C_DIM,
                     z * kspan, (z + 1) * kspan);
}

// ---------------- reduce split-K + bias + normalize -> g_pt[b][c][16] ----
__global__ __launch_bounds__(128) void norm_kernel(const float* __restrict__ b2v) {
    int r = blockIdx.x, t = threadIdx.x;
    int b = r >> 4, n = r & 15;
    float v[10];
    float ss = 0.f;
#pragma unroll
    for (int i = 0; i < 10; i++) {
        int c = t + i * 128;
        size_t o = (size_t)r * C_DIM + c;
        float x = b2v[c];
#pragma unroll
        for (int z = 0; z < KCHUNK; z++)
            x += g_part[o + (size_t)z * M_ROWS * C_DIM];
        v[i] = x;
        ss = fmaf(x, x, ss);
    }
#pragma unroll
    for (int o = 16; o > 0; o >>= 1) ss += __shfl_xor_sync(0xffffffffu, ss, o);
    __shared__ float sw[4];
    if ((t & 31) == 0) sw[t >> 5] = ss;
    __syncthreads();
    float tot = sw[0] + sw[1] + sw[2] + sw[3];
    float scale = 35.7770876f / (sqrtf(tot) + 1e-6f);
#pragma unroll
    for (int i = 0; i < 10; i++) {
        int c = t + i * 128;
        g_pt[((size_t)b * C_DIM + c) * N_ID + n] = v[i] * scale;
    }
}

// ---------------- fused main kernel: cp.async ring, thread-private slots ----------------
// 128 thr, 2 px/thread, 256 px/CTA, grid 288, smem = 80KB tile + 24KB ring, 2 CTAs/SM
__global__ __launch_bounds__(128, 2) void fused_kernel(const float* __restrict__ hidden,
                                                       const float* __restrict__ bboxes,
                                                       float* __restrict__ out) {
    extern __shared__ float sp[];               // [0,20480): p tile; then ring
    __shared__ int sx1[N_ID], sy1[N_ID], sx2[N_ID], sy2[N_ID], semp[N_ID];

    int t = threadIdx.x;
    int blk = blockIdx.x;
    int b = blk / 36;
    int px = (blk % 36) * 256 + 2 * t;          // even; pair never crosses a row

    float* ringf = sp + C_DIM * N_ID;
    unsigned int rbase = (unsigned int)__cvta_generic_to_shared(ringf) + t * 8u;

    const float4* src = (const float4*)(g_pt + (size_t)b * C_DIM * N_ID);
    float4* dst = (float4*)sp;
#pragma unroll
    for (int i = 0; i < 40; i++) dst[t + i * 128] = src[t + i * 128];

    if (t < N_ID) {
        float bx1 = bboxes[t * 4 + 0] * 96.f;
        float by1 = bboxes[t * 4 + 1] * 96.f;
        float bx2 = bboxes[t * 4 + 2] * 96.f;
        float by2 = bboxes[t * 4 + 3] * 96.f;
        int X1 = (int)floorf(fminf(fmaxf(bx1, 0.f), 96.f));
        int Y1 = (int)floorf(fminf(fmaxf(by1, 0.f), 96.f));
        int X2 = (int)floorf(fminf(fmaxf(bx2, 0.f), 96.f));
        int Y2 = (int)floorf(fminf(fmaxf(by2, 0.f), 96.f));
        sx1[t] = X1; sy1[t] = Y1; sx2[t] = X2; sy2[t] = Y2;
        semp[t] = (X1 >= X2) || (Y1 >= Y2);
    }
    __syncthreads();

    int allempty = 1;
#pragma unroll
    for (int n = 0; n < N_ID; n++) allempty &= semp[n];

    int y = px / WIMG;
    int x = px - y * WIMG;
    const float* hp = hidden + (size_t)b * C_DIM * HW + px;

    // ring addressing: slot(stage,ch,t) = stage*8192B + ch*1024B + t*8B
#define ISSUE(G, STG)                                                            \
    {                                                                            \
        const float* gsrc = hp + (size_t)(G) * GCH * HW;                         \
        unsigned int sdst = rbase + (unsigned int)(STG) * 8192u;                 \
        _Pragma("unroll")                                                        \
        for (int ch = 0; ch < GCH; ch++) {                                       \
            asm volatile("cp.async.ca.shared.global [%0], [%1], 8;"              \
                         :: "r"(sdst + ch * 1024u), "l"(gsrc + (size_t)ch * HW)  \
                         : "memory");                                            \
        }                                                                        \
        asm volatile("cp.async.commit_group;" ::: "memory");                     \
    }
#define WAITG(N) asm volatile("cp.async.wait_group %0;" :: "n"(N) : "memory")
#define RINGH(STG, CH) (*(const float2*)(ringf + (STG) * 2048 + (CH) * 256 + t * 2))

    // ---- pass 1: sumsq + 16 dots for 2 px ----
    unsigned long long acc0[8], acc1[8];
#pragma unroll
    for (int k = 0; k < 8; k++) { acc0[k] = 0ull; acc1[k] = 0ull; }
    float ss0 = 0.f, ss1 = 0.f;

#define P1_COMPUTE(G, STG)                                                       \
    {                                                                            \
        _Pragma("unroll")                                                        \
        for (int ch = 0; ch < GCH; ch++) {                                       \
            float2 h = RINGH(STG, ch);                                           \
            ss0 = fmaf(h.x, h.x, ss0);                                           \
            ss1 = fmaf(h.y, h.y, ss1);                                           \
            unsigned long long hx = packf2(h.x, h.x);                            \
            unsigned long long hy = packf2(h.y, h.y);                            \
            const ulonglong2* p2 =                                               \
                (const ulonglong2*)(sp + (((G) * GCH + ch) << 4));               \
            ulonglong2 q0 = p2[0], q1 = p2[1], q2 = p2[2], q3 = p2[3];           \
            acc0[0] = fma2(hx, q0.x, acc0[0]);  acc1[0] = fma2(hy, q0.x, acc1[0]); \
            acc0[1] = fma2(hx, q0.y, acc0[1]);  acc1[1] = fma2(hy, q0.y, acc1[1]); \
            acc0[2] = fma2(hx, q1.x, acc0[2]);  acc1[2] = fma2(hy, q1.x, acc1[2]); \
            acc0[3] = fma2(hx, q1.y, acc0[3]);  acc1[3] = fma2(hy, q1.y, acc1[3]); \
            acc0[4] = fma2(hx, q2.x, acc0[4]);  acc1[4] = fma2(hy, q2.x, acc1[4]); \
            acc0[5] = fma2(hx, q2.y, acc0[5]);  acc1[5] = fma2(hy, q2.y, acc1[5]); \
            acc0[6] = fma2(hx, q3.x, acc0[6]);  acc1[6] = fma2(hy, q3.x, acc1[6]); \
            acc0[7] = fma2(hx, q3.y, acc0[7]);  acc1[7] = fma2(hy, q3.y, acc1[7]); \
        }                                                                        \
    }

    {
        ISSUE(0, 0)
        ISSUE(1, 1)
        int cs = 0;
        for (int g = 0; g < NGRP - 1; g++) {
            WAITG(1);
            P1_COMPUTE(g, cs)
            if (g + 2 < NGRP) {
                int is = cs + 2; if (is >= 3) is -= 3;
                ISSUE(g + 2, is)
            }
            if (++cs == 3) cs = 0;
        }
        WAITG(0);
        P1_COMPUTE(NGRP - 1, cs)
    }

    // ---- weights for both pixels ----
    const float invT = 1.999996f;               // 1/(0.5+1e-6)
    float inv0 = invT / (sqrtf(ss0) + 1e-6f);
    float inv1 = invT / (sqrtf(ss1) + 1e-6f);
    float w0[N_ID], w1[N_ID];
    float sum0 = 0.f, sum1 = 0.f;
#pragma unroll
    for (int k = 0; k < 8; k++) {
        float2 d0 = unpackf2(acc0[k]);
        float2 d1 = unpackf2(acc1[k]);
#pragma unroll
        for (int j = 0; j < 2; j++) {
            int n = 2 * k + j;
            float da = (j == 0) ? d0.x : d0.y;
            float db = (j == 0) ? d1.x : d1.y;
            int ybox = (y >= sy1[n]) & (y < sy2[n]);
            int m0 = allempty | (ybox & (x >= sx1[n]) & (x < sx2[n]));
            int m1 = allempty | (ybox & ((x + 1) >= sx1[n]) & ((x + 1) < sx2[n]));
            float s0 = 1.f / (1.f + __expf(-da * inv0));
            float s1 = 1.f / (1.f + __expf(-db * inv1));
            float wv0 = m0 ? s0 : 0.f;
            float wv1 = m1 ? s1 : 0.f;
            w0[n] = wv0; sum0 += wv0;
            w1[n] = wv1; sum1 += wv1;
        }
    }
    float is0 = 1.f / (sum0 + 1e-6f);
    float is1 = 1.f / (sum1 + 1e-6f);
    unsigned long long wp0[8], wp1[8];
#pragma unroll
    for (int k = 0; k < 8; k++) {
        wp0[k] = packf2(__powf(w0[2 * k] * is0, 1.2f), __powf(w0[2 * k + 1] * is0, 1.2f));
        wp1[k] = packf2(__powf(w1[2 * k] * is1, 1.2f), __powf(w1[2 * k + 1] * is1, 1.2f));
    }

    // ---- pass 2: out = hidden + 1.5*sum_n w[n]*p[n,c] ----
    float* op = out + (size_t)b * C_DIM * HW + px;

#define P2_COMPUTE(G, STG)                                                       \
    {                                                                            \
        _Pragma("unroll")                                                        \
        for (int ch = 0; ch < GCH; ch++) {                                       \
            float2 h = RINGH(STG, ch);                                           \
            const ulonglong2* pq =                                               \
                (const ulonglong2*)(sp + (((G) * GCH + ch) << 4));               \
            ulonglong2 q0 = pq[0], q1 = pq[1], q2 = pq[2], q3 = pq[3];           \
            unsigned long long s0 = 0ull, s1 = 0ull;                             \
            s0 = fma2(wp0[0], q0.x, s0);  s1 = fma2(wp1[0], q0.x, s1);           \
            s0 = fma2(wp0[1], q0.y, s0);  s1 = fma2(wp1[1], q0.y, s1);           \
            s0 = fma2(wp0[2], q1.x, s0);  s1 = fma2(wp1[2], q1.x, s1);           \
            s0 = fma2(wp0[3], q1.y, s0);  s1 = fma2(wp1[3], q1.y, s1);           \
            s0 = fma2(wp0[4], q2.x, s0);  s1 = fma2(wp1[4], q2.x, s1);           \
            s0 = fma2(wp0[5], q2.y, s0);  s1 = fma2(wp1[5], q2.y, s1);           \
            s0 = fma2(wp0[6], q3.x, s0);  s1 = fma2(wp1[6], q3.x, s1);           \
            s0 = fma2(wp0[7], q3.y, s0);  s1 = fma2(wp1[7], q3.y, s1);           \
            float2 a0 = unpackf2(s0), a1 = unpackf2(s1);                         \
            float2 o;                                                            \
            o.x = fmaf(1.5f, a0.x + a0.y, h.x);                                  \
            o.y = fmaf(1.5f, a1.x + a1.y, h.y);                                  \
            __stcs((float2*)(op + (size_t)((G) * GCH + ch) * HW), o);            \
        }                                                                        \
    }

    {
        ISSUE(0, 0)
        ISSUE(1, 1)
        int cs = 0;
        for (int g = 0; g < NGRP - 1; g++) {
            WAITG(1);
            P2_COMPUTE(g, cs)
            if (g + 2 < NGRP) {
                int is = cs + 2; if (is >= 3) is -= 3;
                ISSUE(g + 2, is)
            }
            if (++cs == 3) cs = 0;
        }
        WAITG(0);
        P2_COMPUTE(NGRP - 1, cs)
    }
}

// ---------------- launch ----------------
extern "C" void kernel_launch(void* const* d_in, const int* in_sizes, int n_in,
                              void* d_out, int out_size) {
    const float* hidden = (const float*)d_in[0];
    const float* emb    = (const float*)d_in[1];
    const float* bbox   = (const float*)d_in[2];
    const float* W1     = (const float*)d_in[3];
    const float* b1v    = (const float*)d_in[4];
    const float* W2     = (const float*)d_in[5];
    const float* b2v    = (const float*)d_in[6];
    float* outp = (float*)d_out;

    mlp1_kernel<<<dim3(C_DIM / 64, M_ROWS / 32), 256>>>(emb, W1, b1v);
    mlp2_kernel<<<dim3(C_DIM / 64, M_ROWS / 32, KCHUNK), 256>>>(W2);
    norm_kernel<<<M_ROWS, 128>>>(b2v);

    cudaFuncSetAttribute(fused_kernel, cudaFuncAttributeMaxDynamicSharedMemorySize,
                         SMEM_FLOATS * (int)sizeof(float));
    fused_kernel<<<288, 128, SMEM_FLOATS * sizeof(float)>>>(hidden, bbox, outp);
}